// round 1
// baseline (speedup 1.0000x reference)
#include <cuda_runtime.h>

#define PITCH 129                      // float2 pitch for 128x128 tile (conflict-free cols)
#define NF_MAX 2850                    // >= 2821 masked frequencies
#define SMEM_BYTES (128 * PITCH * sizeof(float2))   // 132096 B

// ---------------- scratch (device globals; no allocation in kernel_launch) ----
__device__ float2 g_E[128];                         // exp(-2*pi*i*k/128)
__device__ int    g_maskUV[NF_MAX];                 // u*128+v, compacted, deterministic order
__device__ float2 g_Xf[(size_t)NF_MAX * 1024];      // [f][b][i]  masked spectrum of x
__device__ float2 g_Yf[(size_t)NF_MAX * 1024];      // [f][b][o]  masked spectrum of out

__device__ __forceinline__ int brev7(int x) { return (int)(__brev((unsigned)x) >> 25); }

// ---------------- init: twiddles + compacted mask list (closed-form rank) -----
__global__ void init_tables() {
    int t = blockIdx.x * blockDim.x + threadIdx.x;
    if (t < 128) {
        double ang = -6.283185307179586476925286766559 * (double)t / 128.0;
        g_E[t] = make_float2((float)cos(ang), (float)sin(ang));
    }
    if (t < 16384) {
        int u = t >> 7, v = t & 127;
        int du = (u < 64) ? u : u - 128;
        int dv = (v < 64) ? v : v - 128;
        if (du * du + dv * dv <= 900) {
            // rank = #masked entries strictly before (u,v) in row-major order
            int rank = 0;
            for (int up = 0; up < u; up++) {
                int dup = (up < 64) ? up : up - 128;
                int rem = 900 - dup * dup;
                if (rem >= 0) {
                    int vm = 0;
                    while ((vm + 1) * (vm + 1) <= rem) vm++;
                    rank += 2 * vm + 1;          // v in [0..vm] U [128-vm..127]
                }
            }
            int rem = 900 - du * du;
            int vm = 0;
            while ((vm + 1) * (vm + 1) <= rem) vm++;
            rank += (v <= vm) ? v : (v - (128 - vm)) + vm + 1;
            g_maskUV[rank] = t;
        }
    }
}

// ---------------- shared-memory 128-pt radix-2 stages over 128 lines ----------
// element j of line L lives at data[L*lineStride + j*elemStride]
__device__ __forceinline__ void fft_stages(float2* data, const float2* tw,
                                           int lineStride, int elemStride,
                                           int tid, int nthreads, bool inverse) {
    for (int s = 1; s <= 7; s++) {
        int half = 1 << (s - 1);
        for (int t = tid; t < 8192; t += nthreads) {
            int line = t >> 6;
            int k    = t & 63;
            int j    = k & (half - 1);
            int pos  = ((k >> (s - 1)) << s) | j;
            float2 w = tw[j << (7 - s)];
            float wy = inverse ? -w.y : w.y;
            int ia = line * lineStride + pos * elemStride;
            int ib = ia + half * elemStride;
            float2 a = data[ia], b = data[ib];
            float2 tv;
            tv.x = w.x * b.x - wy * b.y;
            tv.y = w.x * b.y + wy * b.x;
            data[ia] = make_float2(a.x + tv.x, a.y + tv.y);
            data[ib] = make_float2(a.x - tv.x, a.y - tv.y);
        }
        __syncthreads();
    }
}

// bit-reverse permutation across rows (h <-> brev7(h)), whole rows swapped
__device__ __forceinline__ void bitrev_rows(float2* data, int tid, int nthreads) {
    for (int idx = tid; idx < 16384; idx += nthreads) {
        int h = idx >> 7, w = idx & 127;
        int rh = brev7(h);
        if (h < rh) {
            float2 a = data[h * PITCH + w];
            data[h * PITCH + w]  = data[rh * PITCH + w];
            data[rh * PITCH + w] = a;
        }
    }
    __syncthreads();
}

// ---------------- forward FFT2 per (b,i) image; write masked bins -------------
__global__ __launch_bounds__(512) void fwd_kernel(const float* __restrict__ x, int nMask) {
    extern __shared__ float2 data[];
    __shared__ float2 tw[64];
    int tid = threadIdx.x;
    int img = blockIdx.x;                      // b*64 + i
    if (tid < 64) tw[tid] = g_E[tid];
    const float* src = x + (size_t)img * 16384;
    for (int idx = tid; idx < 16384; idx += 512) {
        int h = idx >> 7, w = idx & 127;
        data[h * PITCH + brev7(w)] = make_float2(src[idx], 0.f);   // pre-permute along w
    }
    __syncthreads();
    fft_stages(data, tw, PITCH, 1, tid, 512, false);   // FFT along w (rows)
    bitrev_rows(data, tid, 512);
    fft_stages(data, tw, 1, PITCH, tid, 512, false);   // FFT along h (cols)
    for (int f = tid; f < nMask; f += 512) {
        int uv = g_maskUV[f];
        g_Xf[(size_t)f * 1024 + img] = data[(uv >> 7) * PITCH + (uv & 127)];
    }
}

// ---------------- per-frequency channel mix: Y[b,o] = sum_i X[b,i]*W[o,i] -----
// W[o,i] computed on the fly from the 3x3 taps (weight FFT = 9-tap twiddle sum)
__global__ __launch_bounds__(256) void mix_kernel(const float* __restrict__ wgt, int nMask) {
    __shared__ float2 Xs[1024];        // [b][i]
    __shared__ float2 Ws[64 * 65];     // [o][i], padded to kill bank conflicts
    __shared__ float2 c9[9];
    int f = blockIdx.x;
    int tid = threadIdx.x;
    int uv = g_maskUV[f];
    if (tid < 9) {
        int p = tid / 3, q = tid % 3;
        int ph = ((uv >> 7) * p + (uv & 127) * q) & 127;
        c9[tid] = g_E[ph];
    }
    for (int i = tid; i < 1024; i += 256) Xs[i] = g_Xf[(size_t)f * 1024 + i];
    __syncthreads();
    for (int oi = tid; oi < 4096; oi += 256) {
        const float* w9 = wgt + oi * 9;
        float2 acc = make_float2(0.f, 0.f);
        #pragma unroll
        for (int k = 0; k < 9; k++) {
            float wv = w9[k];
            acc.x += wv * c9[k].x;
            acc.y += wv * c9[k].y;
        }
        Ws[(oi >> 6) * 65 + (oi & 63)] = acc;
    }
    __syncthreads();
    int o  = tid & 63;
    int bb = (tid >> 6) << 2;          // 4 batches per thread
    float2 a0 = make_float2(0.f, 0.f), a1 = a0, a2 = a0, a3 = a0;
    const float2* wrow = &Ws[o * 65];
    #pragma unroll 8
    for (int i = 0; i < 64; i++) {
        float2 w = wrow[i];
        float2 x0 = Xs[(bb + 0) * 64 + i];
        float2 x1 = Xs[(bb + 1) * 64 + i];
        float2 x2 = Xs[(bb + 2) * 64 + i];
        float2 x3 = Xs[(bb + 3) * 64 + i];
        a0.x += x0.x * w.x - x0.y * w.y;  a0.y += x0.x * w.y + x0.y * w.x;
        a1.x += x1.x * w.x - x1.y * w.y;  a1.y += x1.x * w.y + x1.y * w.x;
        a2.x += x2.x * w.x - x2.y * w.y;  a2.y += x2.x * w.y + x2.y * w.x;
        a3.x += x3.x * w.x - x3.y * w.y;  a3.y += x3.x * w.y + x3.y * w.x;
    }
    size_t base = (size_t)f * 1024;
    g_Yf[base + (bb + 0) * 64 + o] = a0;
    g_Yf[base + (bb + 1) * 64 + o] = a1;
    g_Yf[base + (bb + 2) * 64 + o] = a2;
    g_Yf[base + (bb + 3) * 64 + o] = a3;
}

// ---------------- inverse FFT2 per (b,o); note batch/channel rolls ------------
__global__ __launch_bounds__(512) void inv_kernel(float* __restrict__ out,
                                                  const float* __restrict__ bias, int nMask) {
    extern __shared__ float2 data[];
    __shared__ float2 tw[64];
    int tid = threadIdx.x;
    int img = blockIdx.x;                      // b*64 + o
    int b = img >> 6, o = img & 63;
    int bsrc = (b + 8) & 15;                   // fftshift over batch dim
    int osrc = (o + 32) & 63;                  // fftshift over Cout dim
    if (tid < 64) tw[tid] = g_E[tid];
    for (int idx = tid; idx < 128 * PITCH; idx += 512) data[idx] = make_float2(0.f, 0.f);
    __syncthreads();
    for (int f = tid; f < nMask; f += 512) {
        int uv = g_maskUV[f];
        data[(uv >> 7) * PITCH + brev7(uv & 127)] =
            g_Yf[(size_t)f * 1024 + bsrc * 64 + osrc];   // scatter pre-permuted along v
    }
    __syncthreads();
    fft_stages(data, tw, PITCH, 1, tid, 512, true);      // IFFT along w
    bitrev_rows(data, tid, 512);
    fft_stages(data, tw, 1, PITCH, tid, 512, true);      // IFFT along h
    float bv = bias[o];
    float* dst = out + (size_t)img * 16384;
    const float scale = 1.f / 16384.f;
    for (int idx = tid; idx < 16384; idx += 512) {
        dst[idx] = data[(idx >> 7) * PITCH + (idx & 127)].x * scale + bv;
    }
}

// ---------------- launch -------------------------------------------------------
extern "C" void kernel_launch(void* const* d_in, const int* in_sizes, int n_in,
                              void* d_out, int out_size) {
    const float* x    = (const float*)d_in[0];   // [16,64,128,128]
    const float* wgt  = (const float*)d_in[1];   // [64,64,3,3]
    const float* bias = (const float*)d_in[2];   // [64]
    float* out = (float*)d_out;

    // host-side count of masked frequencies (pure CPU, deterministic)
    int nMask = 0;
    for (int u = 0; u < 128; u++) {
        int du = (u < 64) ? u : u - 128;
        for (int v = 0; v < 128; v++) {
            int dv = (v < 64) ? v : v - 128;
            if (du * du + dv * dv <= 900) nMask++;
        }
    }

    cudaFuncSetAttribute(fwd_kernel, cudaFuncAttributeMaxDynamicSharedMemorySize, (int)SMEM_BYTES);
    cudaFuncSetAttribute(inv_kernel, cudaFuncAttributeMaxDynamicSharedMemorySize, (int)SMEM_BYTES);

    init_tables<<<64, 256>>>();
    fwd_kernel<<<1024, 512, SMEM_BYTES>>>(x, nMask);
    mix_kernel<<<nMask, 256>>>(wgt, nMask);
    inv_kernel<<<1024, 512, SMEM_BYTES>>>(out, bias, nMask);
}

// round 2
// speedup vs baseline: 3.2525x; 3.2525x over previous
#include <cuda_runtime.h>

#define PITCH 129                                   // float2 pitch, conflict-free columns
#define NF_MAX 2850                                 // >= 2821 masked frequencies
#define SMEM_BYTES (128 * PITCH * sizeof(float2))   // 132096 B

// ---------------- device scratch ------------------------------------------------
__device__ float2 g_E[128];                         // exp(-2*pi*i*k/128), exact conj symmetry
__device__ int    g_maskUV[NF_MAX];                 // u*128+v compacted (row-major rank)
__device__ int    g_conjRank[NF_MAX];               // rank of (-u mod 128, -v mod 128)
__device__ float4 g_Xf4[(size_t)NF_MAX * 512];      // [f][b*64+i]/2 masked X spectrum
__device__ float4 g_Yf4[(size_t)NF_MAX * 512];      // [f][b*64+o]/2 masked Y spectrum
#define g_Xf ((float2*)g_Xf4)
#define g_Yf ((float2*)g_Yf4)

__device__ __forceinline__ int brev7(int x) { return (int)(__brev((unsigned)x) >> 25); }
__device__ __forceinline__ float2 cadd(float2 a, float2 b){ return make_float2(a.x+b.x, a.y+b.y); }
__device__ __forceinline__ float2 csub(float2 a, float2 b){ return make_float2(a.x-b.x, a.y-b.y); }
__device__ __forceinline__ float2 cmul(float2 a, float2 b){ return make_float2(a.x*b.x - a.y*b.y, a.x*b.y + a.y*b.x); }
__device__ __forceinline__ float2 cjmul(float2 b, float2 w){ // b * conj(w)
    return make_float2(b.x*w.x + b.y*w.y, b.y*w.x - b.x*w.y); }
__device__ __forceinline__ float2 mulnegi(float2 a){ return make_float2(a.y, -a.x); }
__device__ __forceinline__ float2 mulposi(float2 a){ return make_float2(-a.y, a.x); }

// ---------------- init: twiddles + mask ranks ----------------------------------
__device__ __forceinline__ int vmaxOf(int rem){
    int vm = __float2int_rd(sqrtf((float)rem));
    while (vm*vm > rem) vm--;
    while ((vm+1)*(vm+1) <= rem) vm++;
    return vm;
}
__device__ int rankOf(int u, int v){            // rank among masked bins, row-major
    int rank = 0;
    for (int up = 0; up < u; up++){
        int dup = (up < 64) ? up : up - 128;
        int rem = 900 - dup*dup;
        if (rem >= 0) rank += 2*vmaxOf(rem) + 1;
    }
    int du = (u < 64) ? u : u - 128;
    int vm = vmaxOf(900 - du*du);
    return rank + ((v <= vm) ? v : v - (128 - vm) + vm + 1);
}

__global__ void init_tables(){
    int t = blockIdx.x * blockDim.x + threadIdx.x;
    if (t <= 32){
        double ang = -6.283185307179586476925286766559 * (double)t / 128.0;
        float c = (float)cos(ang), s = (float)sin(ang);       // s <= 0
        if (t == 0)      { g_E[0]  = make_float2(1.f, 0.f);  g_E[64] = make_float2(-1.f, 0.f); }
        else if (t == 32){ g_E[32] = make_float2(0.f, -1.f); g_E[96] = make_float2(0.f, 1.f); }
        else {
            g_E[t]       = make_float2( c,  s);
            g_E[64 - t]  = make_float2(-c,  s);
            g_E[64 + t]  = make_float2(-c, -s);
            g_E[128 - t] = make_float2( c, -s);
        }
    }
    if (t < 16384){
        int u = t >> 7, v = t & 127;
        int du = (u < 64) ? u : u - 128;
        int dv = (v < 64) ? v : v - 128;
        if (du*du + dv*dv <= 900){
            int r = rankOf(u, v);
            g_maskUV[r] = t;
            g_conjRank[r] = rankOf((128 - u) & 127, (128 - v) & 127);
        }
    }
}

// ---------------- fused radix passes (in-place, 512 threads) -------------------
// element m of a butterfly lives at base + m*stride patterns below.

// forward DIF radix-8: stages dist 64,32,16 (h=16), natural-order input
__device__ __forceinline__ void dif8(float2* d, const float2* tw, int ls, int es, int tid){
    #pragma unroll
    for (int it = 0; it < 4; it++){
        int t = tid + it*512;             // 0..2047
        int line = t & 127, j = t >> 7;   // j in [0,16)
        int base = line*ls + j*es, stp = 16*es;
        float2 x[8];
        #pragma unroll
        for (int m = 0; m < 8; m++) x[m] = d[base + m*stp];
        // dist 64: (m, m+4), w = tw[j+16m]
        #pragma unroll
        for (int m = 0; m < 4; m++){
            float2 a = x[m], b = x[m+4];
            x[m] = cadd(a,b);
            x[m+4] = cmul(csub(a,b), tw[j + 16*m]);
        }
        // dist 32: (0,2),(1,3),(4,6),(5,7); w = tw[2j] / tw[2j+32]
        {
            float2 w0 = tw[2*j], w1 = tw[2*j + 32], a, b;
            a=x[0]; b=x[2]; x[0]=cadd(a,b); x[2]=cmul(csub(a,b), w0);
            a=x[1]; b=x[3]; x[1]=cadd(a,b); x[3]=cmul(csub(a,b), w1);
            a=x[4]; b=x[6]; x[4]=cadd(a,b); x[6]=cmul(csub(a,b), w0);
            a=x[5]; b=x[7]; x[5]=cadd(a,b); x[7]=cmul(csub(a,b), w1);
        }
        // dist 16: (m, m+1), w = tw[4j]
        {
            float2 w = tw[4*j];
            #pragma unroll
            for (int m = 0; m < 8; m += 2){
                float2 a = x[m], b = x[m+1];
                x[m] = cadd(a,b); x[m+1] = cmul(csub(a,b), w);
            }
        }
        #pragma unroll
        for (int m = 0; m < 8; m++) d[base + m*stp] = x[m];
    }
    __syncthreads();
}

// forward DIF radix-16: stages dist 8,4,2,1 (h=1), output bit-reversed
__device__ __forceinline__ void dif16(float2* d, const float2* tw, int ls, int es, int tid){
    #pragma unroll
    for (int it = 0; it < 2; it++){
        int t = tid + it*512;             // 0..1023
        int line = t & 127, blk = t >> 7; // blk in [0,8)
        int base = line*ls + blk*16*es;
        float2 x[16];
        #pragma unroll
        for (int m = 0; m < 16; m++) x[m] = d[base + m*es];
        // dist 8: (m, m+8), w = tw[8m]
        #pragma unroll
        for (int m = 0; m < 8; m++){
            float2 a = x[m], b = x[m+8];
            x[m] = cadd(a,b); x[m+8] = cmul(csub(a,b), tw[8*m]);
        }
        // dist 4: (m,m+4) and (m+8,m+12), w = tw[16m]
        #pragma unroll
        for (int m = 0; m < 4; m++){
            float2 w = tw[16*m], a, b;
            a=x[m];   b=x[m+4];  x[m]  =cadd(a,b); x[m+4] =cmul(csub(a,b), w);
            a=x[m+8]; b=x[m+12]; x[m+8]=cadd(a,b); x[m+12]=cmul(csub(a,b), w);
        }
        // dist 2: (4g,4g+2) w=1 ; (4g+1,4g+3) w=-i
        #pragma unroll
        for (int g = 0; g < 4; g++){
            int b0 = 4*g; float2 a, b;
            a=x[b0];   b=x[b0+2]; x[b0]  =cadd(a,b); x[b0+2]=csub(a,b);
            a=x[b0+1]; b=x[b0+3]; x[b0+1]=cadd(a,b); x[b0+3]=mulnegi(csub(a,b));
        }
        // dist 1: (2k,2k+1), w=1
        #pragma unroll
        for (int m = 0; m < 16; m += 2){
            float2 a = x[m], b = x[m+1];
            x[m] = cadd(a,b); x[m+1] = csub(a,b);
        }
        #pragma unroll
        for (int m = 0; m < 16; m++) d[base + m*es] = x[m];
    }
    __syncthreads();
}

// inverse DIT radix-16: stages dist 1,2,4,8 (h=1), bit-reversed input
__device__ __forceinline__ void dit16(float2* d, const float2* tw, int ls, int es, int tid){
    #pragma unroll
    for (int it = 0; it < 2; it++){
        int t = tid + it*512;
        int line = t & 127, blk = t >> 7;
        int base = line*ls + blk*16*es;
        float2 x[16];
        #pragma unroll
        for (int m = 0; m < 16; m++) x[m] = d[base + m*es];
        // dist 1
        #pragma unroll
        for (int m = 0; m < 16; m += 2){
            float2 a = x[m], b = x[m+1];
            x[m] = cadd(a,b); x[m+1] = csub(a,b);
        }
        // dist 2: (4g,4g+2) w=1 ; (4g+1,4g+3) w=+i
        #pragma unroll
        for (int g = 0; g < 4; g++){
            int b0 = 4*g; float2 a, tt;
            a=x[b0];   tt=x[b0+2];          x[b0]  =cadd(a,tt); x[b0+2]=csub(a,tt);
            a=x[b0+1]; tt=mulposi(x[b0+3]); x[b0+1]=cadd(a,tt); x[b0+3]=csub(a,tt);
        }
        // dist 4: (m,m+4),(m+8,m+12), w = conj(tw[16m])
        #pragma unroll
        for (int m = 0; m < 4; m++){
            float2 w = tw[16*m], a, tt;
            a=x[m];   tt=cjmul(x[m+4],  w); x[m]  =cadd(a,tt); x[m+4] =csub(a,tt);
            a=x[m+8]; tt=cjmul(x[m+12], w); x[m+8]=cadd(a,tt); x[m+12]=csub(a,tt);
        }
        // dist 8: (m,m+8), w = conj(tw[8m])
        #pragma unroll
        for (int m = 0; m < 8; m++){
            float2 a = x[m], tt = cjmul(x[m+8], tw[8*m]);
            x[m] = cadd(a,tt); x[m+8] = csub(a,tt);
        }
        #pragma unroll
        for (int m = 0; m < 16; m++) d[base + m*es] = x[m];
    }
    __syncthreads();
}

// inverse DIT radix-8: stages dist 16,32,64 (h=16)
__device__ __forceinline__ void dit8(float2* d, const float2* tw, int ls, int es, int tid){
    #pragma unroll
    for (int it = 0; it < 4; it++){
        int t = tid + it*512;
        int line = t & 127, j = t >> 7;
        int base = line*ls + j*es, stp = 16*es;
        float2 x[8];
        #pragma unroll
        for (int m = 0; m < 8; m++) x[m] = d[base + m*stp];
        // dist 16: (m, m+1), w = conj(tw[4j])
        {
            float2 w = tw[4*j];
            #pragma unroll
            for (int m = 0; m < 8; m += 2){
                float2 a = x[m], tt = cjmul(x[m+1], w);
                x[m] = cadd(a,tt); x[m+1] = csub(a,tt);
            }
        }
        // dist 32: (0,2),(4,6): conj(tw[2j]) ; (1,3),(5,7): conj(tw[2j+32])
        {
            float2 w0 = tw[2*j], w1 = tw[2*j + 32], a, tt;
            a=x[0]; tt=cjmul(x[2], w0); x[0]=cadd(a,tt); x[2]=csub(a,tt);
            a=x[1]; tt=cjmul(x[3], w1); x[1]=cadd(a,tt); x[3]=csub(a,tt);
            a=x[4]; tt=cjmul(x[6], w0); x[4]=cadd(a,tt); x[6]=csub(a,tt);
            a=x[5]; tt=cjmul(x[7], w1); x[5]=cadd(a,tt); x[7]=csub(a,tt);
        }
        // dist 64: (m, m+4), w = conj(tw[j+16m])
        #pragma unroll
        for (int m = 0; m < 4; m++){
            float2 a = x[m], tt = cjmul(x[m+4], tw[j + 16*m]);
            x[m] = cadd(a,tt); x[m+4] = csub(a,tt);
        }
        #pragma unroll
        for (int m = 0; m < 8; m++) d[base + m*stp] = x[m];
    }
    __syncthreads();
}

// ---------------- forward: pack 2 real channels per complex FFT ----------------
__global__ __launch_bounds__(512) void fwd_kernel(const float* __restrict__ x, int nMask){
    extern __shared__ float2 data[];
    __shared__ float2 tw[128];
    int tid = threadIdx.x;
    if (tid < 128) tw[tid] = g_E[tid];
    int b = blockIdx.x >> 5, ip = blockIdx.x & 31;
    int img = b*64 + 2*ip;
    const float* s0 = x + (size_t)img * 16384;
    const float* s1 = s0 + 16384;
    for (int idx = tid; idx < 16384; idx += 512)
        data[(idx >> 7)*PITCH + (idx & 127)] = make_float2(s0[idx], s1[idx]);
    __syncthreads();
    dif8 (data, tw, PITCH, 1, tid);  dif16(data, tw, PITCH, 1, tid);   // rows (w)
    dif8 (data, tw, 1, PITCH, tid);  dif16(data, tw, 1, PITCH, tid);   // cols (h)
    // gather masked PRIMARY bins; Hermitian split of the packed spectrum
    for (int f = tid; f < nMask; f += 512){
        int pr = g_conjRank[f];
        if (pr < f) continue;
        int uv  = g_maskUV[f];
        int uvb = g_maskUV[pr];
        float2 z  = data[brev7(uv  >> 7)*PITCH + brev7(uv  & 127)];
        float2 zc = data[brev7(uvb >> 7)*PITCH + brev7(uvb & 127)];
        float2 X0 = make_float2(0.5f*(z.x + zc.x), 0.5f*(z.y - zc.y));
        float2 X1 = make_float2(0.5f*(z.y + zc.y), 0.5f*(zc.x - z.x));
        size_t base = (size_t)f*1024 + img;
        g_Xf[base]     = X0;
        g_Xf[base + 1] = X1;
    }
}

// ---------------- per-frequency channel mix (primary bins only) ----------------
__global__ __launch_bounds__(256) void mix_kernel(const float* __restrict__ wgt, int nMask){
    __shared__ float2 Xs[1024];      // [b][i]
    __shared__ float2 Ws[64 * 65];   // [o][i]
    __shared__ float2 c9[9];
    int f = blockIdx.x;
    int pr = g_conjRank[f];
    if (pr < f) return;              // conj partner handled by primary block
    int tid = threadIdx.x;
    int uv = g_maskUV[f];
    if (tid < 9){
        int p = tid / 3, q = tid % 3;
        c9[tid] = g_E[((uv >> 7)*p + (uv & 127)*q) & 127];
    }
    for (int i = tid; i < 1024; i += 256) Xs[i] = g_Xf[(size_t)f*1024 + i];
    __syncthreads();
    for (int oi = tid; oi < 4096; oi += 256){
        const float* w9 = wgt + oi*9;
        float2 acc = make_float2(0.f, 0.f);
        #pragma unroll
        for (int k = 0; k < 9; k++){
            float wv = w9[k];
            acc.x += wv * c9[k].x;
            acc.y += wv * c9[k].y;
        }
        Ws[(oi >> 6)*65 + (oi & 63)] = acc;
    }
    __syncthreads();
    int o  = tid & 63;
    int bb = (tid >> 6) << 2;
    float2 a0 = make_float2(0.f,0.f), a1 = a0, a2 = a0, a3 = a0;
    const float2* wrow = &Ws[o * 65];
    #pragma unroll 8
    for (int i = 0; i < 64; i++){
        float2 w  = wrow[i];
        float2 x0 = Xs[(bb+0)*64 + i];
        float2 x1 = Xs[(bb+1)*64 + i];
        float2 x2 = Xs[(bb+2)*64 + i];
        float2 x3 = Xs[(bb+3)*64 + i];
        a0.x += x0.x*w.x - x0.y*w.y;  a0.y += x0.x*w.y + x0.y*w.x;
        a1.x += x1.x*w.x - x1.y*w.y;  a1.y += x1.x*w.y + x1.y*w.x;
        a2.x += x2.x*w.x - x2.y*w.y;  a2.y += x2.x*w.y + x2.y*w.x;
        a3.x += x3.x*w.x - x3.y*w.y;  a3.y += x3.x*w.y + x3.y*w.x;
    }
    size_t bf = (size_t)f*1024, bp = (size_t)pr*1024;
    g_Yf[bf + (bb+0)*64 + o] = a0;
    g_Yf[bf + (bb+1)*64 + o] = a1;
    g_Yf[bf + (bb+2)*64 + o] = a2;
    g_Yf[bf + (bb+3)*64 + o] = a3;
    if (pr != f){
        g_Yf[bp + (bb+0)*64 + o] = make_float2(a0.x, -a0.y);
        g_Yf[bp + (bb+1)*64 + o] = make_float2(a1.x, -a1.y);
        g_Yf[bp + (bb+2)*64 + o] = make_float2(a2.x, -a2.y);
        g_Yf[bp + (bb+3)*64 + o] = make_float2(a3.x, -a3.y);
    }
}

// ---------------- inverse: pack 2 real outputs per complex IFFT ----------------
__global__ __launch_bounds__(512) void inv_kernel(float* __restrict__ out,
                                                  const float* __restrict__ bias, int nMask){
    extern __shared__ float2 data[];
    __shared__ float2 tw[128];
    int tid = threadIdx.x;
    if (tid < 128) tw[tid] = g_E[tid];
    int b = blockIdx.x >> 5, op = blockIdx.x & 31;
    int o0 = 2*op;
    int bsrc = (b + 8) & 15;                 // fftshift over batch dim
    int osrc = (o0 + 32) & 63;               // fftshift over Cout dim (even)
    for (int idx = tid; idx < 128*PITCH; idx += 512) data[idx] = make_float2(0.f, 0.f);
    __syncthreads();
    for (int f = tid; f < nMask; f += 512){
        int uv = g_maskUV[f];
        float4 y = *(const float4*)&g_Yf4[(size_t)f*512 + (bsrc*64 + osrc)/2];
        // Z = Y0 + i*Y1
        data[brev7(uv >> 7)*PITCH + brev7(uv & 127)] = make_float2(y.x - y.w, y.y + y.z);
    }
    __syncthreads();
    dit16(data, tw, PITCH, 1, tid);  dit8(data, tw, PITCH, 1, tid);    // rows (w)
    dit16(data, tw, 1, PITCH, tid);  dit8(data, tw, 1, PITCH, tid);    // cols (h)
    float bv0 = bias[o0], bv1 = bias[o0 + 1];
    float* d0 = out + (size_t)(b*64 + o0) * 16384;
    float* d1 = d0 + 16384;
    const float sc = 1.f / 16384.f;
    for (int idx = tid; idx < 16384; idx += 512){
        float2 v = data[(idx >> 7)*PITCH + (idx & 127)];
        d0[idx] = v.x * sc + bv0;
        d1[idx] = v.y * sc + bv1;
    }
}

// ---------------- launch --------------------------------------------------------
extern "C" void kernel_launch(void* const* d_in, const int* in_sizes, int n_in,
                              void* d_out, int out_size){
    const float* x    = (const float*)d_in[0];
    const float* wgt  = (const float*)d_in[1];
    const float* bias = (const float*)d_in[2];
    float* out = (float*)d_out;

    int nMask = 0;
    for (int u = 0; u < 128; u++){
        int du = (u < 64) ? u : u - 128;
        for (int v = 0; v < 128; v++){
            int dv = (v < 64) ? v : v - 128;
            if (du*du + dv*dv <= 900) nMask++;
        }
    }

    cudaFuncSetAttribute(fwd_kernel, cudaFuncAttributeMaxDynamicSharedMemorySize, (int)SMEM_BYTES);
    cudaFuncSetAttribute(inv_kernel, cudaFuncAttributeMaxDynamicSharedMemorySize, (int)SMEM_BYTES);

    init_tables<<<64, 256>>>();
    fwd_kernel<<<512, 512, SMEM_BYTES>>>(x, nMask);
    mix_kernel<<<nMask, 256>>>(wgt, nMask);
    inv_kernel<<<512, 512, SMEM_BYTES>>>(out, bias, nMask);
}